// round 17
// baseline (speedup 1.0000x reference)
#include <cuda_runtime.h>
#include <cuda_bf16.h>
#include <cstdint>

// KinematicWaveRouting via the scalar transfer function of the 20-segment chain.
//   y_t = y_{t-1} + u_t - sum_{j=0..7} c_j u_{t-20-j},   u = runoff * basin * 50
//   8-tap NegBinomial kernel, two-moment matched (rel err ~1.8e-4, thresh 1e-3).
// One warp per row, lane = 128-step chunk, warm-started 32 steps early.
// Zero-halo (R16): persistent Z buffer holds every chunk's tail slice, fetched
// once; warm FIR reads Z row (lane-1), group 4 consumes Z with no fetch.
// R17: PERSISTENT blocks — grid = 4 x #SM (one resident wave), grid-stride
// loop over row-groups. Warps stay resident: no per-CTA launch/fill overhead
// for waves 2..4. Each iteration is self-contained (cp.async drained to 0).
// 55.3KB smem/block (dynamic), 4 blocks/SM. Tile rows 144B chunk-major;
// 16B cp.async, LDS.128 loads, STS.128 in-place outputs, LDS.128+STG.128.cs
// drain. All smem phases conflict-free.

#define T_LEN    4096
#define CHUNK    128
#define NCHUNK   32
#define RPB      4
#define NTAPS    8
#define TSTRIDE  36                      // floats per tile row (144 bytes)
#define SERIES   (NCHUNK * TSTRIDE)      // 1152 floats per warp-buffer
#define SMEM_BYTES (3 * RPB * SERIES * 4)   // 55296

// -c'_m, m = 20..27 (two-moment matched)
static __device__ constexpr float CNEG[NTAPS] = {
    -0.12252114f, -0.24315331f, -0.25531098f, -0.18722805f,
    -0.10362058f, -0.05167495f, -0.02153122f, -0.01495978f
};
// warm-start weights g'_m = 1 - cumsum(c'), lags 20..26 (g'_27 = 0)
static __device__ constexpr float GW[7] = {
    0.87747886f, 0.63432555f, 0.37901458f, 0.19178653f,
    0.08816595f, 0.03649100f, 0.01495978f
};

__device__ __forceinline__ void cpasync16(uint32_t s, const float* g) {
    asm volatile("cp.async.cg.shared.global [%0], [%1], 16;" :: "r"(s), "l"(g) : "memory");
}
__device__ __forceinline__ void cpcommit() {
    asm volatile("cp.async.commit_group;" ::: "memory");
}
template <int N>
__device__ __forceinline__ void cpwait() {
    asm volatile("cp.async.wait_group %0;" :: "n"(N) : "memory");
}
__device__ __forceinline__ void sts128(uint32_t a, float v0, float v1, float v2, float v3) {
    asm volatile("st.shared.v4.f32 [%0], {%1, %2, %3, %4};"
                 :: "r"(a), "f"(v0), "f"(v1), "f"(v2), "f"(v3) : "memory");
}
__device__ __forceinline__ void stg128cs(float* p, float4 v) {
    asm volatile("st.global.cs.v4.f32 [%0], {%1, %2, %3, %4};"
                 :: "l"(p), "f"(v.x), "f"(v.y), "f"(v.z), "f"(v.w) : "memory");
}

// Prefetch group GIDX (1..4): 8 x 16B cp.async per lane; instruction i covers
// chunks 4i..4i+3. rq = rrow + (lane>>3)*CHUNK + (lane&7)*4 - 32.
// GIDX=4 fetches each chunk's tail slice [96,128) = the Z / halo tile.
#define PREFETCH(TU, GIDX)                                                  \
    do {                                                                    \
        _Pragma("unroll")                                                   \
        for (int i = 0; i < 8; i++)                                         \
            cpasync16((TU) + i * 576, rq + i * 512 + (GIDX) * 32);          \
        cpcommit();                                                         \
    } while (0)

// Load 32 inputs from row `lane` of TB: 8 x LDS.128, conflict-free.
#define LOAD_W(W, TB)                                                       \
    do {                                                                    \
        const float4* r4 = (const float4*)((TB) + lane * TSTRIDE);          \
        _Pragma("unroll")                                                   \
        for (int k = 0; k < 8; k++) {                                       \
            float4 t = r4[k];                                               \
            W[4 * k] = t.x; W[4 * k + 1] = t.y;                             \
            W[4 * k + 2] = t.z; W[4 * k + 3] = t.w;                         \
        }                                                                   \
    } while (0)

// 32 steps as 8 quads; scaled outputs overwrite the lane's own row in place.
#define GROUP_BODY(PREV, CUR, TROWU)                                        \
    do {                                                                    \
        _Pragma("unroll")                                                   \
        for (int qq = 0; qq < 8; qq++) {                                    \
            float vv[4];                                                    \
            _Pragma("unroll")                                               \
            for (int s = 0; s < 4; s++) {                                   \
                const int m = 4 * qq + s;                                   \
                float acc = CUR[m];                                         \
                _Pragma("unroll")                                           \
                for (int j = 0; j < NTAPS; j++) {                           \
                    const int k = m - (20 + j);                             \
                    float w = (k >= 0) ? CUR[k] : PREV[32 + k];             \
                    acc = fmaf(CNEG[j], w, acc);                            \
                }                                                           \
                y += acc;                                                   \
                vv[s] = y * scale;                                          \
            }                                                               \
            sts128((TROWU) + qq * 16, vv[0], vv[1], vv[2], vv[3]);          \
        }                                                                   \
    } while (0)

// Drain group GIDX: lane handles (chunk = 4k + (lane>>3), quad = lane&7):
// LDS.128 from the chunk-major tile, STG.128.cs covering full 128B lines.
#define DRAIN(TB, GIDX)                                                     \
    do {                                                                    \
        const float* sp = (TB) + (lane >> 3) * TSTRIDE + (lane & 7) * 4;    \
        float* gp = odrain + ((GIDX) - 1) * 32;                             \
        _Pragma("unroll")                                                   \
        for (int k = 0; k < 8; k++) {                                       \
            float4 v = *(const float4*)(sp + k * 4 * TSTRIDE);              \
            stg128cs(gp + k * 512, v);                                      \
        }                                                                   \
    } while (0)

__global__ __launch_bounds__(128, 4)
void kinematic_wave_kernel(const float* __restrict__ runoff,
                           const float* __restrict__ basin,
                           float* __restrict__ out,
                           int B)
{
    extern __shared__ __align__(16) float smem[];

    const int warp = threadIdx.x >> 5;
    const int lane = threadIdx.x & 31;
    const int nRG  = (B + RPB - 1) / RPB;            // row-groups (2048)

    float* X = smem + warp * SERIES;
    float* Y = X + RPB * SERIES;
    float* Z = Y + RPB * SERIES;                     // persistent tail/halo tile

    const uint32_t lslot = (uint32_t)((lane >> 3) * 144 + (lane & 7) * 16);
    const uint32_t rslot = (uint32_t)(lane * 144);
    const uint32_t Xu = (uint32_t)__cvta_generic_to_shared(X);
    const uint32_t Yu = Xu + RPB * SERIES * 4;
    const uint32_t Zu = Yu + RPB * SERIES * 4;

    // ---- persistent grid-stride loop over row-groups ----
    for (int rg = blockIdx.x; rg < nRG; rg += gridDim.x) {
        const int row = rg * RPB + warp;
        if (row >= B) continue;                      // warp-uniform

        const float scale = basin[row] * 50.0f;
        const float* __restrict__ rq =
            runoff + (size_t)row * T_LEN + (lane >> 3) * CHUNK + (lane & 7) * 4 - 32;
        float* __restrict__ odrain =
            out + (size_t)row * T_LEN + (lane >> 3) * CHUNK + (lane & 7) * 4;

        float W0[32], W1[32], y;

        // ---- fetch Z (all chunk tails), G1 -> X, G2 -> Y ----
        PREFETCH(Zu + lslot, 4);     // commit 1: Z (tail slices, = halos)
        PREFETCH(Xu + lslot, 1);     // commit 2: group-1 inputs
        PREFETCH(Yu + lslot, 2);     // commit 3: group-2 inputs
        cpwait<2>(); __syncwarp();   // Z landed

        // warm window: Z row (lane-1) = chunk (lane-1) steps [96,128)
        if (lane > 0) {
            LOAD_W(W0, Z - TSTRIDE);
        } else {
#pragma unroll
            for (int j = 0; j < 32; j++) W0[j] = 0.0f;   // chunk 0: t < 0
        }
        // warm FIR: W0[j] = u(t0-32+j), lag = 31-j; y = outlet at t0-1
        {
            float s = 0.0f;
#pragma unroll
            for (int j = 12; j < 32; j++) s += W0[j];                 // lags 0..19
            float s2 = 0.0f;
#pragma unroll
            for (int j = 5; j < 12; j++) s2 = fmaf(GW[11 - j], W0[j], s2); // 20..26
            y = s + s2;
        }

        // ---- group 1: inputs in X ----
        cpwait<1>(); __syncwarp();                   // X landed
        LOAD_W(W1, X);
        GROUP_BODY(W0, W1, Xu + rslot);
        __syncwarp();
        DRAIN(X, 1);
        __syncwarp();
        PREFETCH(Xu + lslot, 3);     // group-3 inputs -> X (post-drain)

        // ---- group 2: inputs in Y ----
        cpwait<1>(); __syncwarp();                   // Y landed
        LOAD_W(W0, Y);
        GROUP_BODY(W1, W0, Yu + rslot);
        __syncwarp();
        DRAIN(Y, 2);

        // ---- group 3: inputs in X ----
        cpwait<0>(); __syncwarp();                   // G3 landed
        LOAD_W(W1, X);
        GROUP_BODY(W0, W1, Xu + rslot);
        __syncwarp();
        DRAIN(X, 3);
        __syncwarp();

        // ---- group 4: inputs already resident in Z (no fetch) ----
        LOAD_W(W0, Z);
        GROUP_BODY(W1, W0, Zu + rslot);
        __syncwarp();
        DRAIN(Z, 4);
        __syncwarp();                                // Z free for next iteration
    }
}

extern "C" void kernel_launch(void* const* d_in, const int* in_sizes, int n_in,
                              void* d_out, int out_size)
{
    const float* runoff = (const float*)d_in[0];   // (B, T) float32
    const float* basin  = (const float*)d_in[1];   // (B, 1) float32
    float* out = (float*)d_out;                    // (B, T) float32

    int B = in_sizes[1];                           // 8192
    int nRG = (B + RPB - 1) / RPB;                 // 2048 row-groups

    // One resident wave: 4 blocks per SM (smem-capped occupancy).
    int nsm = 148;
    cudaDeviceGetAttribute(&nsm, cudaDevAttrMultiProcessorCount, 0);
    int blocks = 4 * nsm;
    if (blocks > nRG) blocks = nRG;

    // 55.3KB dynamic smem (> 48KB static limit); attribute set is immediate
    // (not a stream op) and deterministic -> graph-capture safe.
    cudaFuncSetAttribute(kinematic_wave_kernel,
                         cudaFuncAttributeMaxDynamicSharedMemorySize, SMEM_BYTES);
    kinematic_wave_kernel<<<blocks, 128, SMEM_BYTES>>>(runoff, basin, out, B);
}